// round 14
// baseline (speedup 1.0000x reference)
#include <cuda_runtime.h>
#include <cuda_bf16.h>

// JointBilateral upsample, S=4, K=5. One thread = 8 output pixels: rows
// {4p+gsel, 4p+gsel+2}, cols 4q..4q+3. Both rows share tap values, x values
// and index math. No smem, no barrier; taps are warm-L2 hit loads.
// 64-thread blocks (2 warps: gsel0/gsel1), 2048 blocks for finer balance.
//
// e(tap) = exp(-0.125*||g_tap - g_ctr||^2) * exp(-0.005*((i-2)^2+(j-2)^2))
// out = sum(e * wgt[4-i][4-j] * x_tap) / sum(e)
// MUFU-free: cubic exp(-z) for z in [0,0.094], Newton reciprocal.

#define CH  (512 * 512)
#define E1  0.9950124791926823f   /* exp(-0.005) */
#define E4  0.9801986733067553f   /* exp(-0.020) */

__device__ __forceinline__ float exp_neg_small(float z)
{
    float p = fmaf(-0.16666667f, z, 0.5f);
    p = fmaf(p, z, -1.0f);
    return fmaf(p, z, 1.0f);
}

__device__ __forceinline__ float fast_rcp(float x)
{
    float r = __uint_as_float(0x7EF311C3u - __float_as_uint(x));
    r = r * fmaf(-x, r, 2.0f);
    r = r * fmaf(-x, r, 2.0f);
    return r;
}

__global__ void __launch_bounds__(64) jb_kernel(
    const float* __restrict__ x,
    const float* __restrict__ g,
    const float* __restrict__ wgt,
    float* __restrict__ out)
{
    int tid  = threadIdx.x;
    int ql   = tid & 31;
    int gsel = tid >> 5;              // 0: rows {0,2}; 1: rows {1,3}
    int blk  = blockIdx.x;            // 2048 = 4 qh * 128 p * 4 b
    int qh   = blk & 3;
    int p    = (blk >> 2) & 127;
    int b    = blk >> 9;
    int q    = qh * 32 + ql;

    const float* gb = g + (size_t)b * 3 * CH;
    const float* xb = x + b * (128 * 128);

    bool row2 = (p < 127);
    bool col2 = (q < 127);
    int dq = col2 ? 4 : 0;
    int cq = col2 ? 1 : 0;

    int rowA = (4 * p + gsel) * 512 + 4 * q;
    int rowB = rowA + 2 * 512;
    int o00  = (4 * p + 1) * 512 + 4 * q + 1;

    // ---- front-loaded loads ----
    float4 a0 = *(const float4*)(gb + rowA);
    float4 a1 = *(const float4*)(gb + CH + rowA);
    float4 a2 = *(const float4*)(gb + 2 * CH + rowA);
    float4 e0 = *(const float4*)(gb + rowB);
    float4 e1 = *(const float4*)(gb + CH + rowB);
    float4 e2 = *(const float4*)(gb + 2 * CH + rowB);

    float t0 = gb[o00];
    float t1 = gb[o00 + CH];
    float t2 = gb[o00 + 2 * CH];
    float u0 = gb[o00 + dq];
    float u1 = gb[o00 + dq + CH];
    float u2 = gb[o00 + dq + 2 * CH];

    int xo = p * 128 + q;
    float x00 = xb[xo];
    float x01 = xb[xo + cq];

    // second-row taps only needed by gsel==1 (row 4p+3); warp-uniform branch
    float v0 = 0.f, v1 = 0.f, v2 = 0.f, z0 = 0.f, z1 = 0.f, z2 = 0.f;
    float x10 = 0.f, x11 = 0.f;
    if (gsel == 1) {
        int dr = row2 ? 4 * 512 : 0;
        v0 = gb[o00 + dr];
        v1 = gb[o00 + dr + CH];
        v2 = gb[o00 + dr + 2 * CH];
        z0 = gb[o00 + dr + dq];
        z1 = gb[o00 + dr + dq + CH];
        z2 = gb[o00 + dr + dq + 2 * CH];
        int cp = row2 ? 1 : 0;
        x10 = xb[xo + cp * 128];
        x11 = xb[xo + cp * 128 + cq];
    }

    const float espC[4]    = {E1, 1.0f, E1, E4};
    const float espSTab[4] = {E1, 1.0f, E1, E4};
    size_t obase = (size_t)b * CH;

    // ================= row A (sp = gsel) =================
    {
        int sp = gsel;
        float espS = espSTab[sp];
        const float* wr = wgt + (sp + 1) * 5;
        float wAr[4] = {wr[1] * x00, wr[2] * x00, wr[3] * x00, wr[4] * x00};
        float wCol = wr[0] * x01;
        float ctr0[4] = {a0.x, a0.y, a0.z, a0.w};
        float ctr1[4] = {a1.x, a1.y, a1.z, a1.w};
        float ctr2[4] = {a2.x, a2.y, a2.z, a2.w};

        float num[4], den[4];
#pragma unroll
        for (int r = 0; r < 4; r++) {
            float d0 = t0 - ctr0[r];
            float d1 = t1 - ctr1[r];
            float d2 = t2 - ctr2[r];
            float zv = 0.125f * fmaf(d0, d0, fmaf(d1, d1, d2 * d2));
            float e = exp_neg_small(zv) * (espS * espC[r]);
            den[r] = e;
            num[r] = e * wAr[r];
        }
        {
            float h0 = u0 - ctr0[3];
            float h1 = u1 - ctr1[3];
            float h2 = u2 - ctr2[3];
            float zv = 0.125f * fmaf(h0, h0, fmaf(h1, h1, h2 * h2));
            float e3 = exp_neg_small(zv) * (espS * E4);
            if (col2) { den[3] += e3; num[3] += e3 * wCol; }
        }
        float4 o = make_float4(num[0] * fast_rcp(den[0]),
                               num[1] * fast_rcp(den[1]),
                               num[2] * fast_rcp(den[2]),
                               num[3] * fast_rcp(den[3]));
        *(float4*)(out + obase + rowA) = o;
    }

    // ================= row B (sp = gsel + 2) =================
    {
        int sp = gsel + 2;
        float espS = espSTab[sp];
        const float* wr = wgt + (sp + 1) * 5;
        float wAr[4] = {wr[1] * x00, wr[2] * x00, wr[3] * x00, wr[4] * x00};
        float wCol = wr[0] * x01;
        float ctr0[4] = {e0.x, e0.y, e0.z, e0.w};
        float ctr1[4] = {e1.x, e1.y, e1.z, e1.w};
        float ctr2[4] = {e2.x, e2.y, e2.z, e2.w};

        float num[4], den[4];
#pragma unroll
        for (int r = 0; r < 4; r++) {
            float d0 = t0 - ctr0[r];
            float d1 = t1 - ctr1[r];
            float d2 = t2 - ctr2[r];
            float zv = 0.125f * fmaf(d0, d0, fmaf(d1, d1, d2 * d2));
            float e = exp_neg_small(zv) * (espS * espC[r]);
            den[r] = e;
            num[r] = e * wAr[r];
        }
        {
            float h0 = u0 - ctr0[3];
            float h1 = u1 - ctr1[3];
            float h2 = u2 - ctr2[3];
            float zv = 0.125f * fmaf(h0, h0, fmaf(h1, h1, h2 * h2));
            float e3 = exp_neg_small(zv) * (espS * E4);
            if (col2) { den[3] += e3; num[3] += e3 * wCol; }
        }

        if (gsel == 1 && row2) {      // row 4p+3: second-row taps (warp-uniform)
#pragma unroll
            for (int r = 0; r < 4; r++) {
                float f0 = v0 - ctr0[r];
                float f1 = v1 - ctr1[r];
                float f2 = v2 - ctr2[r];
                float zv = 0.125f * fmaf(f0, f0, fmaf(f1, f1, f2 * f2));
                float e2x = exp_neg_small(zv) * (E4 * espC[r]);
                den[r] += e2x;
                num[r] += e2x * wgt[r + 1] * x10;
            }
            if (col2) {               // corner tap
                float k0 = z0 - ctr0[3];
                float k1 = z1 - ctr1[3];
                float k2 = z2 - ctr2[3];
                float zz = 0.125f * fmaf(k0, k0, fmaf(k1, k1, k2 * k2));
                float e4x = exp_neg_small(zz) * (E4 * E4);
                den[3] += e4x;
                num[3] += e4x * wgt[0] * x11;
            }
        }

        float4 o = make_float4(num[0] * fast_rcp(den[0]),
                               num[1] * fast_rcp(den[1]),
                               num[2] * fast_rcp(den[2]),
                               num[3] * fast_rcp(den[3]));
        *(float4*)(out + obase + rowB) = o;
    }
}

extern "C" void kernel_launch(void* const* d_in, const int* in_sizes, int n_in,
                              void* d_out, int out_size)
{
    const float* x   = (const float*)d_in[0];
    const float* g   = (const float*)d_in[1];
    const float* wgt = (const float*)d_in[2];
    float* out = (float*)d_out;

    // 2048 blocks: 4 qh * 128 p * 4 b ; 64 threads: 2 row-groups * 32 q
    jb_kernel<<<2048, 64>>>(x, g, wgt, out);
}

// round 15
// speedup vs baseline: 1.0140x; 1.0140x over previous
#include <cuda_runtime.h>
#include <cuda_bf16.h>

// JointBilateral upsample, S=4, K=5. R10 skeleton (best measured: 1024 blocks
// x 128 threads, 8 px/thread rows {4p+gsel, 4p+gsel+2}, no smem/barrier) with
// the tap math rewritten in packed f32x2 (FFMA2): column pixels (r0,r1) and
// (r2,r3) are processed as one 64-bit lane pair. Subtract = fma2(c, -1, t);
// exp(-0.125*s) as cubic poly in s (0.125 folded into coefficients).
// Col/corner taps (r=3 only) stay scalar; divides on MUFU.

#define CH  (512 * 512)
#define E1  0.9950124791926823f   /* exp(-0.005) */
#define E4  0.9801986733067553f   /* exp(-0.020) */

typedef unsigned long long u64;

__device__ __forceinline__ u64 pk2(float lo, float hi)
{
    u64 r; asm("mov.b64 %0, {%1,%2};" : "=l"(r) : "f"(lo), "f"(hi)); return r;
}
__device__ __forceinline__ void up2(u64 v, float& lo, float& hi)
{
    asm("mov.b64 {%0,%1}, %2;" : "=f"(lo), "=f"(hi) : "l"(v));
}
__device__ __forceinline__ u64 fma2(u64 a, u64 b, u64 c)
{
    u64 d; asm("fma.rn.f32x2 %0, %1, %2, %3;" : "=l"(d) : "l"(a), "l"(b), "l"(c)); return d;
}
__device__ __forceinline__ u64 add2(u64 a, u64 b)
{
    u64 d; asm("add.rn.f32x2 %0, %1, %2;" : "=l"(d) : "l"(a), "l"(b)); return d;
}
__device__ __forceinline__ u64 mul2(u64 a, u64 b)
{
    u64 d; asm("mul.rn.f32x2 %0, %1, %2;" : "=l"(d) : "l"(a), "l"(b)); return d;
}

// exp(-0.125*s) for s in [0, 0.75]: cubic, coefficients absorb the 0.125
#define PC1 (-0.125f)
#define PC2 (0.0078125f)
#define PC3 (-3.2552083e-4f)

__device__ __forceinline__ float exp_s(float s)
{
    float p = fmaf(PC3, s, PC2);
    p = fmaf(p, s, PC1);
    return fmaf(p, s, 1.0f);
}

__global__ void __launch_bounds__(128) jb_kernel(
    const float* __restrict__ x,
    const float* __restrict__ g,
    const float* __restrict__ wgt,
    float* __restrict__ out)
{
    int tid  = threadIdx.x;
    int ql   = tid & 63;
    int gsel = tid >> 6;              // 0: rows {0,2}; 1: rows {1,3}
    int blk  = blockIdx.x;            // 1024 = 2 qh * 128 p * 4 b
    int qh   = blk & 1;
    int p    = (blk >> 1) & 127;
    int b    = blk >> 8;
    int q    = qh * 64 + ql;

    const float* gb = g + (size_t)b * 3 * CH;
    const float* xb = x + b * (128 * 128);

    bool row2 = (p < 127);
    bool col2 = (q < 127);
    int dq = col2 ? 4 : 0;
    int cq = col2 ? 1 : 0;

    int rowA = (4 * p + gsel) * 512 + 4 * q;
    int rowB = rowA + 2 * 512;
    int o00  = (4 * p + 1) * 512 + 4 * q + 1;

    // ---- front-loaded loads ----
    float4 a0 = *(const float4*)(gb + rowA);
    float4 a1 = *(const float4*)(gb + CH + rowA);
    float4 a2 = *(const float4*)(gb + 2 * CH + rowA);
    float4 e0 = *(const float4*)(gb + rowB);
    float4 e1 = *(const float4*)(gb + CH + rowB);
    float4 e2 = *(const float4*)(gb + 2 * CH + rowB);

    float t0 = gb[o00];
    float t1 = gb[o00 + CH];
    float t2 = gb[o00 + 2 * CH];
    float u0 = gb[o00 + dq];
    float u1 = gb[o00 + dq + CH];
    float u2 = gb[o00 + dq + 2 * CH];

    int xo = p * 128 + q;
    float x00 = xb[xo];
    float x01 = xb[xo + cq];

    float v0 = 0.f, v1 = 0.f, v2 = 0.f, zc0 = 0.f, zc1 = 0.f, zc2 = 0.f;
    float x10 = 0.f, x11 = 0.f;
    if (gsel == 1) {                  // warp-uniform
        int dr = row2 ? 4 * 512 : 0;
        v0 = gb[o00 + dr];
        v1 = gb[o00 + dr + CH];
        v2 = gb[o00 + dr + 2 * CH];
        zc0 = gb[o00 + dr + dq];
        zc1 = gb[o00 + dr + dq + CH];
        zc2 = gb[o00 + dr + dq + 2 * CH];
        int cp = row2 ? 1 : 0;
        x10 = xb[xo + cp * 128];
        x11 = xb[xo + cp * 128 + cq];
    }

    // packed constants / broadcasts
    const u64 NEG1 = pk2(-1.0f, -1.0f);
    const u64 ONE2 = pk2(1.0f, 1.0f);
    const u64 C1v  = pk2(PC1, PC1);
    const u64 C2v  = pk2(PC2, PC2);
    const u64 C3v  = pk2(PC3, PC3);
    u64 T0 = pk2(t0, t0), T1 = pk2(t1, t1), T2 = pk2(t2, t2);

    size_t obase = (size_t)b * CH;

    float espSA = (gsel == 1) ? 1.0f : E1;   // rowA: sp = gsel
    float espSB = (gsel == 1) ? E4 : E1;     // rowB: sp = gsel + 2

#pragma unroll
    for (int half = 0; half < 2; half++) {
        float4 c0 = (half == 0) ? a0 : e0;
        float4 c1 = (half == 0) ? a1 : e1;
        float4 c2 = (half == 0) ? a2 : e2;
        float espS = (half == 0) ? espSA : espSB;
        int sp = (half == 0) ? gsel : gsel + 2;
        const float* wr = wgt + (sp + 1) * 5;
        int orow = (half == 0) ? rowA : rowB;

        u64 C0a = pk2(c0.x, c0.y), C0b = pk2(c0.z, c0.w);
        u64 C1a = pk2(c1.x, c1.y), C1b = pk2(c1.z, c1.w);
        u64 C2a = pk2(c2.x, c2.y), C2b = pk2(c2.z, c2.w);

        u64 WXa = pk2(wr[1] * x00, wr[2] * x00);
        u64 WXb = pk2(wr[3] * x00, wr[4] * x00);
        u64 ESPa = pk2(espS * E1, espS);
        u64 ESPb = pk2(espS * E1, espS * E4);

        // ---- first tap, pair a (r0,r1) ----
        u64 d0 = fma2(C0a, NEG1, T0);
        u64 d1 = fma2(C1a, NEG1, T1);
        u64 d2 = fma2(C2a, NEG1, T2);
        u64 sA = mul2(d0, d0);
        sA = fma2(d1, d1, sA);
        sA = fma2(d2, d2, sA);
        u64 pA = fma2(C3v, sA, C2v);
        pA = fma2(pA, sA, C1v);
        pA = fma2(pA, sA, ONE2);
        u64 eA = mul2(pA, ESPa);
        u64 denA = eA;
        u64 numA = mul2(eA, WXa);

        // ---- first tap, pair b (r2,r3) ----
        d0 = fma2(C0b, NEG1, T0);
        d1 = fma2(C1b, NEG1, T1);
        d2 = fma2(C2b, NEG1, T2);
        u64 sB = mul2(d0, d0);
        sB = fma2(d1, d1, sB);
        sB = fma2(d2, d2, sB);
        u64 pB = fma2(C3v, sB, C2v);
        pB = fma2(pB, sB, C1v);
        pB = fma2(pB, sB, ONE2);
        u64 eB = mul2(pB, ESPb);
        u64 denB = eB;
        u64 numB = mul2(eB, WXb);

        if (gsel == 1 && half == 1 && row2) {   // row 4p+3: second-row taps
            u64 V0 = pk2(v0, v0), V1 = pk2(v1, v1), V2 = pk2(v2, v2);
            u64 WX2a = pk2(wgt[1] * x10, wgt[2] * x10);
            u64 WX2b = pk2(wgt[3] * x10, wgt[4] * x10);
            u64 ESP2a = pk2(E4 * E1, E4);
            u64 ESP2b = pk2(E4 * E1, E4 * E4);

            u64 f0 = fma2(C0a, NEG1, V0);
            u64 f1 = fma2(C1a, NEG1, V1);
            u64 f2 = fma2(C2a, NEG1, V2);
            u64 s2 = mul2(f0, f0);
            s2 = fma2(f1, f1, s2);
            s2 = fma2(f2, f2, s2);
            u64 p2 = fma2(C3v, s2, C2v);
            p2 = fma2(p2, s2, C1v);
            p2 = fma2(p2, s2, ONE2);
            u64 e2p = mul2(p2, ESP2a);
            denA = add2(denA, e2p);
            numA = fma2(e2p, WX2a, numA);

            f0 = fma2(C0b, NEG1, V0);
            f1 = fma2(C1b, NEG1, V1);
            f2 = fma2(C2b, NEG1, V2);
            s2 = mul2(f0, f0);
            s2 = fma2(f1, f1, s2);
            s2 = fma2(f2, f2, s2);
            p2 = fma2(C3v, s2, C2v);
            p2 = fma2(p2, s2, C1v);
            p2 = fma2(p2, s2, ONE2);
            e2p = mul2(p2, ESP2b);
            denB = add2(denB, e2p);
            numB = fma2(e2p, WX2b, numB);
        }

        float den0, den1, den2f, den3, num0, num1, num2f, num3;
        up2(denA, den0, den1);
        up2(numA, num0, num1);
        up2(denB, den2f, den3);
        up2(numB, num2f, num3);

        if (col2) {   // second-col tap for r=3 (scalar)
            float h0 = u0 - c0.w;
            float h1 = u1 - c1.w;
            float h2 = u2 - c2.w;
            float sc = fmaf(h0, h0, fmaf(h1, h1, h2 * h2));
            float e3 = exp_s(sc) * (espS * E4);
            den3 += e3;
            num3 = fmaf(e3, wr[0] * x01, num3);

            if (gsel == 1 && half == 1 && row2) {   // corner tap
                float k0 = zc0 - c0.w;
                float k1 = zc1 - c1.w;
                float k2 = zc2 - c2.w;
                float sk = fmaf(k0, k0, fmaf(k1, k1, k2 * k2));
                float e4x = exp_s(sk) * (E4 * E4);
                den3 += e4x;
                num3 = fmaf(e4x, wgt[0] * x11, num3);
            }
        }

        float4 o = make_float4(__fdividef(num0, den0),
                               __fdividef(num1, den1),
                               __fdividef(num2f, den2f),
                               __fdividef(num3, den3));
        *(float4*)(out + obase + orow) = o;
    }
}

extern "C" void kernel_launch(void* const* d_in, const int* in_sizes, int n_in,
                              void* d_out, int out_size)
{
    const float* x   = (const float*)d_in[0];
    const float* g   = (const float*)d_in[1];
    const float* wgt = (const float*)d_in[2];
    float* out = (float*)d_out;

    // 1024 blocks: 2 qh * 128 p * 4 b ; 128 threads: 2 row-groups * 64 q
    jb_kernel<<<1024, 128>>>(x, g, wgt, out);
}